// round 2
// baseline (speedup 1.0000x reference)
#include <cuda_runtime.h>
#include <math.h>

#define BB 2048
#define TT 200
#define FF 128
#define HH 256
#define GG 1024   // 4*H
#define OO 6
#define MC 8      // batch rows per CTA
#define NTH 256
#define NCTA (BB / MC)

// Scratch: permutation of batch rows sorted by length (grouping only; per-row
// math is independent of grouping, so output is deterministic).
__device__ int d_perm[BB];

__global__ void sort_kernel(const int* __restrict__ lengths) {
    __shared__ int hist[TT + 1];   // lengths in [1, 200]
    int tid = threadIdx.x;
    for (int i = tid; i <= TT; i += blockDim.x) hist[i] = 0;
    __syncthreads();
    for (int b = tid; b < BB; b += blockDim.x) atomicAdd(&hist[lengths[b]], 1);
    __syncthreads();
    if (tid == 0) {
        int acc = 0;
        for (int i = 0; i <= TT; i++) { int c = hist[i]; hist[i] = acc; acc += c; }
    }
    __syncthreads();
    for (int b = tid; b < BB; b += blockDim.x) {
        int pos = atomicAdd(&hist[lengths[b]], 1);
        d_perm[pos] = b;
    }
}

// ---------- accurate activations (immune to fast-math flags) ----------
// Cody-Waite exp, degree-7 Taylor on |r| <= ln2/2; abs err ~2e-8.
__device__ __forceinline__ float exp_acc(float x) {
    x = fminf(fmaxf(x, -87.0f), 87.0f);
    float n = rintf(x * 1.4426950408889634f);
    float r = fmaf(n, -0.693359375f, x);        // ln2_hi
    r = fmaf(n, 2.12194440e-4f, r);             // ln2_lo
    float p = 1.98412698e-4f;                   // 1/5040
    p = fmaf(p, r, 1.38888889e-3f);             // 1/720
    p = fmaf(p, r, 8.33333333e-3f);             // 1/120
    p = fmaf(p, r, 4.16666667e-2f);             // 1/24
    p = fmaf(p, r, 1.66666667e-1f);             // 1/6
    p = fmaf(p, r, 0.5f);
    p = fmaf(p, r, 1.0f);
    p = fmaf(p, r, 1.0f);
    int ni = (int)n;
    float scale = __int_as_float((ni + 127) << 23);
    return p * scale;
}
__device__ __forceinline__ float sig_acc(float v) {
    return __frcp_rn(1.0f + exp_acc(-v));       // correctly-rounded rcp
}
__device__ __forceinline__ float tanh_acc(float x) {
    float a = fabsf(x);
    float u = __frcp_rn(exp_acc(2.0f * a) + 1.0f);
    float t = fmaf(-2.0f, u, 1.0f);
    return copysignf(t, x);
}

__global__ __launch_bounds__(NTH, 2) void lstm_kernel(
    const float* __restrict__ x, const int* __restrict__ lengths,
    const float* __restrict__ W1, const float* __restrict__ b1,
    const float* __restrict__ W2, const float* __restrict__ b2,
    const float* __restrict__ Wout, const float* __restrict__ bout,
    float* __restrict__ out)
{
    __shared__ float A1[MC][FF + HH];   // [x_t | h1]  8x384
    __shared__ float A2[MC][2 * HH];    // [h1  | h2]  8x512
    __shared__ int rows[MC];
    __shared__ int lens[MC];
    __shared__ int smax;

    const int tid = threadIdx.x;
    const int n = tid;                  // hidden unit owned by this thread
    const int cta = blockIdx.x;

    if (tid < MC) {
        int r = d_perm[cta * MC + tid];
        rows[tid] = r;
        lens[tid] = lengths[r];
    }
    for (int i = tid; i < MC * (FF + HH); i += NTH) ((float*)A1)[i] = 0.0f;
    for (int i = tid; i < MC * 2 * HH; i += NTH) ((float*)A2)[i] = 0.0f;
    __syncthreads();
    if (tid == 0) {
        int mx = 0;
        for (int m = 0; m < MC; m++) mx = max(mx, lens[m]);
        smax = mx;
    }
    __syncthreads();

    int lenr[MC];
    #pragma unroll
    for (int m = 0; m < MC; m++) lenr[m] = lens[m];
    const int maxlen = smax;

    // Hoist biases (gate order: i, j, f, o)
    const float bi1 = b1[n], bj1 = b1[HH + n], bf1 = b1[2 * HH + n], bo1 = b1[3 * HH + n];
    const float bi2 = b2[n], bj2 = b2[HH + n], bf2 = b2[2 * HH + n], bo2 = b2[3 * HH + n];

    float c1[MC], c2[MC], sum[MC];
    #pragma unroll
    for (int m = 0; m < MC; m++) { c1[m] = 0.f; c2[m] = 0.f; sum[m] = 0.f; }

    const float* w1p = W1 + n;
    const float* w2p = W2 + n;

    for (int t = 0; t < maxlen; t++) {
        // Load x_t for the 8 rows. Safe: nobody reads A1's x-region right now.
        for (int i = tid; i < MC * FF; i += NTH) {
            int m = i >> 7;          // /128
            int f = i & 127;
            A1[m][f] = x[(size_t)rows[m] * (TT * FF) + t * FF + f];
        }
        __syncthreads();

        // ---------- Layer 1 GEMM: z1 = [x_t, h1] @ W1 + b1 ----------
        float ai[MC], aj[MC], af[MC], ao[MC];
        #pragma unroll
        for (int m = 0; m < MC; m++) { ai[m] = bi1; aj[m] = bj1; af[m] = bf1; ao[m] = bo1; }

        #pragma unroll 1
        for (int k = 0; k < FF + HH; k += 4) {
            #pragma unroll
            for (int kk = 0; kk < 4; kk++) {
                const float* wr = w1p + (size_t)(k + kk) * GG;
                float wi = wr[0], wj = wr[HH], wf = wr[2 * HH], wo = wr[3 * HH];
                #pragma unroll
                for (int m = 0; m < MC; m++) {
                    float a = A1[m][k + kk];
                    ai[m] = fmaf(a, wi, ai[m]);
                    aj[m] = fmaf(a, wj, aj[m]);
                    af[m] = fmaf(a, wf, af[m]);
                    ao[m] = fmaf(a, wo, ao[m]);
                }
            }
        }
        // Elementwise layer 1: compute in registers only (no smem writes yet)
        float nh1[MC];
        #pragma unroll
        for (int m = 0; m < MC; m++) {
            float ig = sig_acc(ai[m]);
            float jg = tanh_acc(aj[m]);
            float fg = sig_acc(af[m] + 1.0f);
            float og = sig_acc(ao[m]);
            float nc = c1[m] * fg + ig * jg;
            if (t < lenr[m]) c1[m] = nc;
            nh1[m] = tanh_acc(nc) * og;
        }
        __syncthreads();   // ALL layer-1 GEMM reads done before h1 is overwritten

        #pragma unroll
        for (int m = 0; m < MC; m++) {
            if (t < lenr[m]) {
                A1[m][FF + n] = nh1[m];   // h1 for next step's layer-1 input
                A2[m][n]      = nh1[m];   // h1 for this step's layer-2 input
            }
        }
        __syncthreads();

        // ---------- Layer 2 GEMM: z2 = [h1, h2] @ W2 + b2 ----------
        #pragma unroll
        for (int m = 0; m < MC; m++) { ai[m] = bi2; aj[m] = bj2; af[m] = bf2; ao[m] = bo2; }
        #pragma unroll 1
        for (int k = 0; k < 2 * HH; k += 4) {
            #pragma unroll
            for (int kk = 0; kk < 4; kk++) {
                const float* wr = w2p + (size_t)(k + kk) * GG;
                float wi = wr[0], wj = wr[HH], wf = wr[2 * HH], wo = wr[3 * HH];
                #pragma unroll
                for (int m = 0; m < MC; m++) {
                    float a = A2[m][k + kk];
                    ai[m] = fmaf(a, wi, ai[m]);
                    aj[m] = fmaf(a, wj, aj[m]);
                    af[m] = fmaf(a, wf, af[m]);
                    ao[m] = fmaf(a, wo, ao[m]);
                }
            }
        }
        // Elementwise layer 2 in registers
        float nh2[MC];
        #pragma unroll
        for (int m = 0; m < MC; m++) {
            float ig = sig_acc(ai[m]);
            float jg = tanh_acc(aj[m]);
            float fg = sig_acc(af[m] + 1.0f);
            float og = sig_acc(ao[m]);
            float nc = c2[m] * fg + ig * jg;
            if (t < lenr[m]) c2[m] = nc;
            nh2[m] = tanh_acc(nc) * og;
        }
        __syncthreads();   // ALL layer-2 GEMM reads done before h2 is overwritten

        #pragma unroll
        for (int m = 0; m < MC; m++) {
            if (t < lenr[m]) {
                sum[m] += nh2[m];
                A2[m][HH + n] = nh2[m];   // h2 for next step
            }
        }
        // No barrier needed here: next x-load writes only A1's x-region,
        // which nothing reads until after the barrier that follows it.
    }

    __syncthreads();
    // Final projection: logits = (sum/len) @ Wout + bout
    #pragma unroll
    for (int m = 0; m < MC; m++) A2[m][n] = sum[m];
    __syncthreads();

    if (tid < MC * OO) {
        int m = tid / OO, o = tid % OO;
        float acc = 0.f;
        for (int k = 0; k < HH; k++) acc = fmaf(A2[m][k], Wout[k * OO + o], acc);
        out[rows[m] * OO + o] = acc / (float)lens[m] + bout[o];
    }
}

extern "C" void kernel_launch(void* const* d_in, const int* in_sizes, int n_in,
                              void* d_out, int out_size) {
    const float* x       = (const float*)d_in[0];
    const int*   lengths = (const int*)  d_in[1];
    const float* W1      = (const float*)d_in[2];
    const float* b1      = (const float*)d_in[3];
    const float* W2      = (const float*)d_in[4];
    const float* b2      = (const float*)d_in[5];
    const float* Wout    = (const float*)d_in[6];
    const float* bout    = (const float*)d_in[7];
    float* out = (float*)d_out;

    sort_kernel<<<1, NTH>>>(lengths);
    lstm_kernel<<<NCTA, NTH>>>(x, lengths, W1, b1, W2, b2, Wout, bout, out);
}

// round 3
// speedup vs baseline: 1.3847x; 1.3847x over previous
#include <cuda_runtime.h>
#include <math.h>

#define BB 2048
#define TT 200
#define FF 128
#define HH 256
#define GG 1024   // 4*H
#define OO 6
#define MC 8      // batch rows per CTA
#define NTH 256
#define NCTA (BB / MC)
#define K1 (FF + HH)   // 384
#define K2 (2 * HH)    // 512

// Scratch: permutation of batch rows sorted by length.
__device__ int d_perm[BB];
// Gate-interleaved weights: [k][n] -> float4(wi, wj, wf, wo)
__device__ float4 d_W1v[K1 * HH];
__device__ float4 d_W2v[K2 * HH];

__global__ void sort_kernel(const int* __restrict__ lengths) {
    __shared__ int hist[TT + 1];   // lengths in [1, 200]
    int tid = threadIdx.x;
    for (int i = tid; i <= TT; i += blockDim.x) hist[i] = 0;
    __syncthreads();
    for (int b = tid; b < BB; b += blockDim.x) atomicAdd(&hist[lengths[b]], 1);
    __syncthreads();
    if (tid == 0) {
        int acc = 0;
        for (int i = 0; i <= TT; i++) { int c = hist[i]; hist[i] = acc; acc += c; }
    }
    __syncthreads();
    for (int b = tid; b < BB; b += blockDim.x) {
        int pos = atomicAdd(&hist[lengths[b]], 1);
        d_perm[pos] = b;
    }
}

__global__ void pack_kernel(const float* __restrict__ W1, const float* __restrict__ W2) {
    int idx = blockIdx.x * blockDim.x + threadIdx.x;
    if (idx < K1 * HH) {
        int k = idx >> 8, n = idx & 255;
        const float* r = W1 + (size_t)k * GG;
        d_W1v[idx] = make_float4(r[n], r[HH + n], r[2 * HH + n], r[3 * HH + n]);
    }
    if (idx < K2 * HH) {
        int k = idx >> 8, n = idx & 255;
        const float* r = W2 + (size_t)k * GG;
        d_W2v[idx] = make_float4(r[n], r[HH + n], r[2 * HH + n], r[3 * HH + n]);
    }
}

// ---------- accurate activations (immune to fast-math flags) ----------
__device__ __forceinline__ float exp_acc(float x) {
    x = fminf(fmaxf(x, -87.0f), 87.0f);
    float n = rintf(x * 1.4426950408889634f);
    float r = fmaf(n, -0.693359375f, x);
    r = fmaf(n, 2.12194440e-4f, r);
    float p = 1.98412698e-4f;
    p = fmaf(p, r, 1.38888889e-3f);
    p = fmaf(p, r, 8.33333333e-3f);
    p = fmaf(p, r, 4.16666667e-2f);
    p = fmaf(p, r, 1.66666667e-1f);
    p = fmaf(p, r, 0.5f);
    p = fmaf(p, r, 1.0f);
    p = fmaf(p, r, 1.0f);
    float scale = __int_as_float(((int)n + 127) << 23);
    return p * scale;
}
__device__ __forceinline__ float sig_acc(float v) {
    return __frcp_rn(1.0f + exp_acc(-v));
}
__device__ __forceinline__ float tanh_acc(float x) {
    float a = fabsf(x);
    float u = __frcp_rn(exp_acc(2.0f * a) + 1.0f);
    float t = fmaf(-2.0f, u, 1.0f);
    return copysignf(t, x);
}

// One 4-k group of FMAs: av carries 4 activations, w0..w3 the 4 packed gate cols.
#define GROUP_FMA(Asrc, kbase)                                              \
    _Pragma("unroll")                                                       \
    for (int m = 0; m < MC; m++) {                                          \
        float4 av = *(const float4*)&Asrc[m][kbase];                        \
        ai[m] = fmaf(av.x, w0.x, ai[m]); aj[m] = fmaf(av.x, w0.y, aj[m]);   \
        af[m] = fmaf(av.x, w0.z, af[m]); ao[m] = fmaf(av.x, w0.w, ao[m]);   \
        ai[m] = fmaf(av.y, w1.x, ai[m]); aj[m] = fmaf(av.y, w1.y, aj[m]);   \
        af[m] = fmaf(av.y, w1.z, af[m]); ao[m] = fmaf(av.y, w1.w, ao[m]);   \
        ai[m] = fmaf(av.z, w2.x, ai[m]); aj[m] = fmaf(av.z, w2.y, aj[m]);   \
        af[m] = fmaf(av.z, w2.z, af[m]); ao[m] = fmaf(av.z, w2.w, ao[m]);   \
        ai[m] = fmaf(av.w, w3.x, ai[m]); aj[m] = fmaf(av.w, w3.y, aj[m]);   \
        af[m] = fmaf(av.w, w3.z, af[m]); ao[m] = fmaf(av.w, w3.w, ao[m]);   \
    }

__global__ __launch_bounds__(NTH, 2) void lstm_kernel(
    const float* __restrict__ x, const int* __restrict__ lengths,
    const float* __restrict__ b1, const float* __restrict__ b2,
    const float* __restrict__ Wout, const float* __restrict__ bout,
    float* __restrict__ out)
{
    __shared__ __align__(16) float A1[MC][K1];   // [x_t | h1]
    __shared__ __align__(16) float A2[MC][K2];   // [h1  | h2]
    __shared__ int rows[MC];
    __shared__ int lens[MC];
    __shared__ int smax;

    const int tid = threadIdx.x;
    const int n = tid;
    const int cta = blockIdx.x;

    if (tid < MC) {
        int r = d_perm[cta * MC + tid];
        rows[tid] = r;
        lens[tid] = lengths[r];
    }
    for (int i = tid; i < MC * K1; i += NTH) ((float*)A1)[i] = 0.0f;
    for (int i = tid; i < MC * K2; i += NTH) ((float*)A2)[i] = 0.0f;
    __syncthreads();
    if (tid == 0) {
        int mx = 0;
        for (int m = 0; m < MC; m++) mx = max(mx, lens[m]);
        smax = mx;
    }
    __syncthreads();

    int lenr[MC];
    #pragma unroll
    for (int m = 0; m < MC; m++) lenr[m] = lens[m];
    const int maxlen = smax;

    const float bi1 = b1[n], bj1 = b1[HH + n], bf1 = b1[2 * HH + n], bo1 = b1[3 * HH + n];
    const float bi2 = b2[n], bj2 = b2[HH + n], bf2 = b2[2 * HH + n], bo2 = b2[3 * HH + n];

    float c1[MC], c2[MC], sum[MC];
    #pragma unroll
    for (int m = 0; m < MC; m++) { c1[m] = 0.f; c2[m] = 0.f; sum[m] = 0.f; }

    const float4* __restrict__ w1p = d_W1v + n;   // stride HH per k
    const float4* __restrict__ w2p = d_W2v + n;

    for (int t = 0; t < maxlen; t++) {
        // Load x_t: 8 rows x 32 float4 = exactly one float4 per thread
        {
            int m = tid >> 5, f = tid & 31;
            ((float4*)A1[m])[f] =
                ((const float4*)(x + (size_t)rows[m] * (TT * FF) + (size_t)t * FF))[f];
        }
        __syncthreads();

        // ---------- Layer 1: z1 = [x_t, h1] @ W1 + b1 ----------
        float ai[MC], aj[MC], af[MC], ao[MC];
        #pragma unroll
        for (int m = 0; m < MC; m++) { ai[m] = bi1; aj[m] = bj1; af[m] = bf1; ao[m] = bo1; }
        {
            float4 w0 = w1p[0 * HH], w1 = w1p[1 * HH], w2 = w1p[2 * HH], w3 = w1p[3 * HH];
            #pragma unroll 1
            for (int k = 0; k < K1; k += 4) {
                int kn = (k + 4 < K1) ? (k + 4) : 0;    // branch-free prefetch
                float4 p0 = w1p[(kn + 0) * HH], p1 = w1p[(kn + 1) * HH],
                       p2 = w1p[(kn + 2) * HH], p3 = w1p[(kn + 3) * HH];
                GROUP_FMA(A1, k)
                w0 = p0; w1 = p1; w2 = p2; w3 = p3;
            }
        }
        float nh1[MC];
        #pragma unroll
        for (int m = 0; m < MC; m++) {
            float ig = sig_acc(ai[m]);
            float jg = tanh_acc(aj[m]);
            float fg = sig_acc(af[m] + 1.0f);
            float og = sig_acc(ao[m]);
            float nc = c1[m] * fg + ig * jg;
            if (t < lenr[m]) c1[m] = nc;
            nh1[m] = tanh_acc(nc) * og;
        }
        __syncthreads();   // all layer-1 reads done before h1 overwrite

        #pragma unroll
        for (int m = 0; m < MC; m++) {
            if (t < lenr[m]) {
                A1[m][FF + n] = nh1[m];
                A2[m][n]      = nh1[m];
            }
        }
        __syncthreads();

        // ---------- Layer 2: z2 = [h1, h2] @ W2 + b2 ----------
        #pragma unroll
        for (int m = 0; m < MC; m++) { ai[m] = bi2; aj[m] = bj2; af[m] = bf2; ao[m] = bo2; }
        {
            float4 w0 = w2p[0 * HH], w1 = w2p[1 * HH], w2 = w2p[2 * HH], w3 = w2p[3 * HH];
            #pragma unroll 1
            for (int k = 0; k < K2; k += 4) {
                int kn = (k + 4 < K2) ? (k + 4) : 0;
                float4 p0 = w2p[(kn + 0) * HH], p1 = w2p[(kn + 1) * HH],
                       p2 = w2p[(kn + 2) * HH], p3 = w2p[(kn + 3) * HH];
                GROUP_FMA(A2, k)
                w0 = p0; w1 = p1; w2 = p2; w3 = p3;
            }
        }
        float nh2[MC];
        #pragma unroll
        for (int m = 0; m < MC; m++) {
            float ig = sig_acc(ai[m]);
            float jg = tanh_acc(aj[m]);
            float fg = sig_acc(af[m] + 1.0f);
            float og = sig_acc(ao[m]);
            float nc = c2[m] * fg + ig * jg;
            if (t < lenr[m]) c2[m] = nc;
            nh2[m] = tanh_acc(nc) * og;
        }
        __syncthreads();   // all layer-2 reads done before h2 overwrite

        #pragma unroll
        for (int m = 0; m < MC; m++) {
            if (t < lenr[m]) {
                sum[m] += nh2[m];
                A2[m][HH + n] = nh2[m];
            }
        }
        // next x-load touches only A1's x-region; barrier after it protects reads
    }

    __syncthreads();
    #pragma unroll
    for (int m = 0; m < MC; m++) A2[m][n] = sum[m];
    __syncthreads();

    if (tid < MC * OO) {
        int m = tid / OO, o = tid % OO;
        float acc = 0.f;
        for (int k = 0; k < HH; k++) acc = fmaf(A2[m][k], Wout[k * OO + o], acc);
        out[rows[m] * OO + o] = acc / (float)lens[m] + bout[o];
    }
}

extern "C" void kernel_launch(void* const* d_in, const int* in_sizes, int n_in,
                              void* d_out, int out_size) {
    const float* x       = (const float*)d_in[0];
    const int*   lengths = (const int*)  d_in[1];
    const float* W1      = (const float*)d_in[2];
    const float* b1      = (const float*)d_in[3];
    const float* W2      = (const float*)d_in[4];
    const float* b2      = (const float*)d_in[5];
    const float* Wout    = (const float*)d_in[6];
    const float* bout    = (const float*)d_in[7];
    float* out = (float*)d_out;

    sort_kernel<<<1, NTH>>>(lengths);
    pack_kernel<<<(K2 * HH + 255) / 256, 256>>>(W1, W2);
    lstm_kernel<<<NCTA, NTH>>>(x, lengths, b1, b2, Wout, bout, out);
}